// round 13
// baseline (speedup 1.0000x reference)
#include <cuda_runtime.h>
#include <cuda_fp16.h>
#include <cstdint>

#define SQ 2048
#define DH 64
#define BQ 128
#define BK 64
#define LDB 144          // smem row stride in bytes (72 fp16) -> conflict-free ldmatrix

// smem layout: Q (fp16) persistent, then two K/V buffers (fp16)
#define OFF_QHI 0                    // 128 rows * 144B = 18432
#define OFF_KV0 18432                // each buffer: KHI+0, VHI+9216
#define KV_SZ   18432
#define REL_KHI 0
#define REL_VHI 9216
#define SMEM_SZ (OFF_KV0 + 2 * KV_SZ)   // 55296

#define MAXB 64
__device__ int g_perm[MAXB];

__device__ __forceinline__ float ex2f(float x) {
    float r; asm("ex2.approx.f32 %0, %1;" : "=f"(r) : "f"(x)); return r;
}
__device__ __forceinline__ uint32_t smem_u32(const void* p) {
    uint32_t a;
    asm("{ .reg .u64 t; cvta.to.shared.u64 t, %1; cvt.u32.u64 %0, t; }" : "=r"(a) : "l"(p));
    return a;
}
__device__ __forceinline__ uint32_t hpack2(float x0, float x1) {
    __half2 h = __floats2half2_rn(x0, x1);
    return *reinterpret_cast<uint32_t*>(&h);
}
__device__ __forceinline__ void ldsm4(uint32_t a, uint32_t* r) {
    asm volatile("ldmatrix.sync.aligned.m8n8.x4.shared.b16 {%0,%1,%2,%3}, [%4];"
                 : "=r"(r[0]), "=r"(r[1]), "=r"(r[2]), "=r"(r[3]) : "r"(a));
}
__device__ __forceinline__ void ldsm4t(uint32_t a, uint32_t* r) {
    asm volatile("ldmatrix.sync.aligned.m8n8.x4.trans.shared.b16 {%0,%1,%2,%3}, [%4];"
                 : "=r"(r[0]), "=r"(r[1]), "=r"(r[2]), "=r"(r[3]) : "r"(a));
}
__device__ __forceinline__ void mma16816(float* d, const uint32_t* a, const uint32_t* b) {
    asm volatile("mma.sync.aligned.m16n8k16.row.col.f32.f16.f16.f32 "
                 "{%0,%1,%2,%3}, {%4,%5,%6,%7}, {%8,%9}, {%0,%1,%2,%3};"
                 : "+f"(d[0]), "+f"(d[1]), "+f"(d[2]), "+f"(d[3])
                 : "r"(a[0]), "r"(a[1]), "r"(a[2]), "r"(a[3]), "r"(b[0]), "r"(b[1]));
}
// store prefetched K/V tile (fp32 in regs) as fp16 into smem buffer
__device__ __forceinline__ void split_store(const float4* pre, char* smc,
                                            uint32_t bufoff, int tid) {
    #pragma unroll
    for (int it = 0; it < 4; it++) {
        int idx = tid + (it << 8);              // 1024 float4 slots = 64x64
        int r = idx >> 4, d4 = (idx & 15) << 2;
        uint32_t off = bufoff + (uint32_t)(r * LDB + (d4 << 1));
        *(uint2*)(smc + off + REL_KHI) =
            make_uint2(hpack2(pre[it].x, pre[it].y), hpack2(pre[it].z, pre[it].w));
        *(uint2*)(smc + off + REL_VHI) =
            make_uint2(hpack2(pre[4 + it].x, pre[4 + it].y),
                       hpack2(pre[4 + it].z, pre[4 + it].w));
    }
}

// LPT scheduling: rank batches by descending tile count (ties by index).
__global__ void make_perm(const int* __restrict__ VL, int B) {
    int i = threadIdx.x;
    if (i >= B) return;
    int ti = (VL[i] + BK - 1) >> 6;
    int rank = 0;
    for (int j = 0; j < B; j++) {
        int tj = (VL[j] + BK - 1) >> 6;
        if (tj > ti || (tj == ti && j < i)) rank++;
    }
    g_perm[rank] = i;
}

__global__ void __launch_bounds__(256, 1)
fa_hmma(const float* __restrict__ Q, const float* __restrict__ K,
        const float* __restrict__ V, const int* __restrict__ VL,
        float* __restrict__ O)
{
    extern __shared__ __align__(128) char smc[];
    const uint32_t sb = smem_u32(smc);

    const int tid  = threadIdx.x;
    const int wid  = tid >> 5;
    const int lane = tid & 31;
    const int b    = g_perm[blockIdx.y];       // LPT-ordered batch
    const int q0   = blockIdx.x * BQ;
    const int valid = VL[b];

    const float* Qb = Q + ((size_t)b * SQ + q0) * DH;
    const float* Kb = K + (size_t)b * SQ * DH;
    const float* Vb = V + (size_t)b * SQ * DH;
    float*       Ob = O + ((size_t)b * SQ + q0) * DH;

    const int ntiles = (valid + BK - 1) >> 6;   // masked tiles contribute exactly 0

    // ---- prologue: issue tile-0 K/V loads (latency hidden behind Q staging) ----
    float4 pre[8];
    #pragma unroll
    for (int it = 0; it < 4; it++) {
        int idx = tid + (it << 8);
        int r = idx >> 4, d4 = (idx & 15) << 2;
        pre[it]     = *(const float4*)(Kb + (size_t)r * DH + d4);
        pre[4 + it] = *(const float4*)(Vb + (size_t)r * DH + d4);
    }

    // ---- stage Q (scaled by log2e/sqrt(D)) as fp16 into persistent smem ----
    const float qs = 1.4426950408889634f / 8.0f;
    #pragma unroll
    for (int it = 0; it < 8; it++) {
        int idx = tid + (it << 8);              // 2048 float4 slots = 128x64
        int r = idx >> 4, d4 = (idx & 15) << 2;
        float4 qv = *(const float4*)(Qb + r * DH + d4);
        uint32_t off = (uint32_t)(r * LDB + (d4 << 1));
        *(uint2*)(smc + OFF_QHI + off) =
            make_uint2(hpack2(qv.x * qs, qv.y * qs), hpack2(qv.z * qs, qv.w * qs));
    }

    split_store(pre, smc, OFF_KV0, tid);        // tile 0 -> buffer 0
    __syncthreads();

    // ---- Q fragments persistent in registers ----
    uint32_t qh[4][4];
    {
        uint32_t qa = sb + (uint32_t)((wid * 16 + (lane & 15)) * LDB
                                      + (((lane >> 4) << 3) << 1));
        #pragma unroll
        for (int kt4 = 0; kt4 < 4; kt4++)
            ldsm4(qa + OFF_QHI + (uint32_t)((kt4 * 16) << 1), qh[kt4]);
    }

    float oacc[8][4];
    #pragma unroll
    for (int j = 0; j < 8; j++)
        #pragma unroll
        for (int i = 0; i < 4; i++) oacc[j][i] = 0.f;
    float ls0 = 0.f, ls1 = 0.f;

    for (int kt = 0; kt < ntiles; kt++) {
        const int k0 = kt << 6;
        const uint32_t kvb = OFF_KV0 + (uint32_t)(kt & 1) * KV_SZ;
        const bool have_next = (kt + 1 < ntiles);
        const bool full = (k0 + BK <= valid);

        // ---- prefetch next tile's K/V into registers ----
        if (have_next) {
            const int k0n = k0 + BK;
            #pragma unroll
            for (int it = 0; it < 4; it++) {
                int idx = tid + (it << 8);
                int r = idx >> 4, d4 = (idx & 15) << 2;
                pre[it]     = *(const float4*)(Kb + (size_t)(k0n + r) * DH + d4);
                pre[4 + it] = *(const float4*)(Vb + (size_t)(k0n + r) * DH + d4);
            }
        }

        // ---- fused tile body: 4 stages, each = GEMM1(2 j-groups) + softmax + GEMM2(step t)
        //      interleaves MUFU/cvt work between MMA issues instead of phase bursts
        #pragma unroll
        for (int t = 0; t < 4; t++) {
            uint32_t Ah[4];
            #pragma unroll
            for (int u = 0; u < 2; u++) {
                const int j = 2 * t + u;
                float sacc[4] = {0.f, 0.f, 0.f, 0.f};
                uint32_t kh[8];
                uint32_t a = sb + kvb
                           + (uint32_t)((j * 8 + (lane & 7)) * LDB + (((lane >> 3) << 3) << 1));
                ldsm4(a + REL_KHI, kh); ldsm4(a + REL_KHI + 64, kh + 4);
                #pragma unroll
                for (int kt4 = 0; kt4 < 4; kt4++) mma16816(sacc, qh[kt4], kh + 2 * kt4);

                float p0 = ex2f(sacc[0]), p1 = ex2f(sacc[1]);
                float p2 = ex2f(sacc[2]), p3 = ex2f(sacc[3]);
                if (!full) {
                    int key0 = k0 + j * 8 + ((lane & 3) << 1);
                    if (key0     >= valid) { p0 = 0.f; p2 = 0.f; }
                    if (key0 + 1 >= valid) { p1 = 0.f; p3 = 0.f; }
                }
                ls0 += p0 + p1; ls1 += p2 + p3;
                Ah[2 * u]     = hpack2(p0, p1);
                Ah[2 * u + 1] = hpack2(p2, p3);
            }

            // GEMM2 K-step t consumes exactly the P of j=2t,2t+1
            int vrow = t * 16 + (((lane >> 3) & 1) << 3) + (lane & 7);
            #pragma unroll
            for (int j2 = 0; j2 < 4; j2++) {
                uint32_t vh[4];
                uint32_t a = sb + kvb
                           + (uint32_t)(vrow * LDB + ((j2 * 16 + ((lane >> 4) << 3)) << 1));
                ldsm4t(a + REL_VHI, vh);
                mma16816(oacc[2*j2],     Ah, vh);
                mma16816(oacc[2*j2 + 1], Ah, vh + 2);
            }
        }

        // ---- write next tile into the other buffer; one barrier per tile ----
        if (have_next)
            split_store(pre, smc, OFF_KV0 + (uint32_t)((kt + 1) & 1) * KV_SZ, tid);
        __syncthreads();
    }

    // ---- reduce l across the 4 lanes sharing each row, normalize, store ----
    ls0 += __shfl_xor_sync(0xffffffffu, ls0, 1);
    ls0 += __shfl_xor_sync(0xffffffffu, ls0, 2);
    ls1 += __shfl_xor_sync(0xffffffffu, ls1, 1);
    ls1 += __shfl_xor_sync(0xffffffffu, ls1, 2);
    float inv0 = 1.0f / ls0, inv1 = 1.0f / ls1;

    int g = lane >> 2, c = lane & 3;
    float* r0p = Ob + (wid * 16 + g) * DH;
    float* r1p = r0p + 8 * DH;
    #pragma unroll
    for (int j = 0; j < 8; j++) {
        int col = j * 8 + 2 * c;
        *(float2*)(r0p + col) = make_float2(oacc[j][0] * inv0, oacc[j][1] * inv0);
        *(float2*)(r1p + col) = make_float2(oacc[j][2] * inv1, oacc[j][3] * inv1);
    }
}

extern "C" void kernel_launch(void* const* d_in, const int* in_sizes, int n_in,
                              void* d_out, int out_size) {
    const float* Q  = (const float*)d_in[0];
    const float* K  = (const float*)d_in[1];
    const float* V  = (const float*)d_in[2];
    const int*   VL = (const int*)d_in[3];
    float*       O  = (float*)d_out;
    const int B = in_sizes[3] <= MAXB ? in_sizes[3] : MAXB;

    make_perm<<<1, MAXB>>>(VL, B);

    cudaFuncSetAttribute(fa_hmma, cudaFuncAttributeMaxDynamicSharedMemorySize, SMEM_SZ);
    dim3 grid(SQ / BQ, B);
    fa_hmma<<<grid, 256, SMEM_SZ>>>(Q, K, V, VL, O);
}

// round 14
// speedup vs baseline: 1.0137x; 1.0137x over previous
#include <cuda_runtime.h>
#include <cuda_fp16.h>
#include <cstdint>

#define SQ 2048
#define DH 64
#define BQ 128
#define BK 64
#define LDB 144          // smem row stride in bytes (72 fp16) -> conflict-free ldmatrix

// smem layout: Q (fp16) persistent, then two K/V buffers (fp16)
#define OFF_QHI 0                    // 128 rows * 144B = 18432
#define OFF_KV0 18432                // each buffer: KHI+0, VHI+9216
#define KV_SZ   18432
#define REL_KHI 0
#define REL_VHI 9216
#define SMEM_SZ (OFF_KV0 + 2 * KV_SZ)   // 55296

#define MAXB 64
__device__ int g_perm[MAXB];

__device__ __forceinline__ float ex2f(float x) {
    float r; asm("ex2.approx.f32 %0, %1;" : "=f"(r) : "f"(x)); return r;
}
__device__ __forceinline__ uint32_t smem_u32(const void* p) {
    uint32_t a;
    asm("{ .reg .u64 t; cvta.to.shared.u64 t, %1; cvt.u32.u64 %0, t; }" : "=r"(a) : "l"(p));
    return a;
}
__device__ __forceinline__ uint32_t hpack2(float x0, float x1) {
    __half2 h = __floats2half2_rn(x0, x1);
    return *reinterpret_cast<uint32_t*>(&h);
}
__device__ __forceinline__ void ldsm4(uint32_t a, uint32_t* r) {
    asm volatile("ldmatrix.sync.aligned.m8n8.x4.shared.b16 {%0,%1,%2,%3}, [%4];"
                 : "=r"(r[0]), "=r"(r[1]), "=r"(r[2]), "=r"(r[3]) : "r"(a));
}
__device__ __forceinline__ void ldsm4t(uint32_t a, uint32_t* r) {
    asm volatile("ldmatrix.sync.aligned.m8n8.x4.trans.shared.b16 {%0,%1,%2,%3}, [%4];"
                 : "=r"(r[0]), "=r"(r[1]), "=r"(r[2]), "=r"(r[3]) : "r"(a));
}
__device__ __forceinline__ void mma16816(float* d, const uint32_t* a, const uint32_t* b) {
    asm volatile("mma.sync.aligned.m16n8k16.row.col.f32.f16.f16.f32 "
                 "{%0,%1,%2,%3}, {%4,%5,%6,%7}, {%8,%9}, {%0,%1,%2,%3};"
                 : "+f"(d[0]), "+f"(d[1]), "+f"(d[2]), "+f"(d[3])
                 : "r"(a[0]), "r"(a[1]), "r"(a[2]), "r"(a[3]), "r"(b[0]), "r"(b[1]));
}
// store prefetched K/V tile (fp32 in regs) as fp16 into smem buffer
__device__ __forceinline__ void split_store(const float4* pre, char* smc,
                                            uint32_t bufoff, int tid) {
    #pragma unroll
    for (int it = 0; it < 4; it++) {
        int idx = tid + (it << 8);              // 1024 float4 slots = 64x64
        int r = idx >> 4, d4 = (idx & 15) << 2;
        uint32_t off = bufoff + (uint32_t)(r * LDB + (d4 << 1));
        *(uint2*)(smc + off + REL_KHI) =
            make_uint2(hpack2(pre[it].x, pre[it].y), hpack2(pre[it].z, pre[it].w));
        *(uint2*)(smc + off + REL_VHI) =
            make_uint2(hpack2(pre[4 + it].x, pre[4 + it].y),
                       hpack2(pre[4 + it].z, pre[4 + it].w));
    }
}

// LPT scheduling: rank batches by descending tile count (ties by index).
__global__ void make_perm(const int* __restrict__ VL, int B) {
    int i = threadIdx.x;
    if (i >= B) return;
    int ti = (VL[i] + BK - 1) >> 6;
    int rank = 0;
    for (int j = 0; j < B; j++) {
        int tj = (VL[j] + BK - 1) >> 6;
        if (tj > ti || (tj == ti && j < i)) rank++;
    }
    g_perm[rank] = i;
}

__global__ void __launch_bounds__(256, 1)
fa_hmma(const float* __restrict__ Q, const float* __restrict__ K,
        const float* __restrict__ V, const int* __restrict__ VL,
        float* __restrict__ O)
{
    extern __shared__ __align__(128) char smc[];
    const uint32_t sb = smem_u32(smc);

    const int tid  = threadIdx.x;
    const int wid  = tid >> 5;
    const int lane = tid & 31;
    const int b    = g_perm[blockIdx.y];       // LPT-ordered batch
    const int q0   = blockIdx.x * BQ;
    const int valid = VL[b];

    const float* Qb = Q + ((size_t)b * SQ + q0) * DH;
    const float* Kb = K + (size_t)b * SQ * DH;
    const float* Vb = V + (size_t)b * SQ * DH;
    float*       Ob = O + ((size_t)b * SQ + q0) * DH;

    const int ntiles = (valid + BK - 1) >> 6;   // masked tiles contribute exactly 0

    // ---- prologue: issue tile-0 K/V loads (latency hidden behind Q staging) ----
    float4 pre[8];
    #pragma unroll
    for (int it = 0; it < 4; it++) {
        int idx = tid + (it << 8);
        int r = idx >> 4, d4 = (idx & 15) << 2;
        pre[it]     = *(const float4*)(Kb + (size_t)r * DH + d4);
        pre[4 + it] = *(const float4*)(Vb + (size_t)r * DH + d4);
    }

    // ---- stage Q (scaled by log2e/sqrt(D)) as fp16 into persistent smem ----
    const float qs = 1.4426950408889634f / 8.0f;
    #pragma unroll
    for (int it = 0; it < 8; it++) {
        int idx = tid + (it << 8);              // 2048 float4 slots = 128x64
        int r = idx >> 4, d4 = (idx & 15) << 2;
        float4 qv = *(const float4*)(Qb + r * DH + d4);
        uint32_t off = (uint32_t)(r * LDB + (d4 << 1));
        *(uint2*)(smc + OFF_QHI + off) =
            make_uint2(hpack2(qv.x * qs, qv.y * qs), hpack2(qv.z * qs, qv.w * qs));
    }

    split_store(pre, smc, OFF_KV0, tid);        // tile 0 -> buffer 0
    __syncthreads();

    // ---- Q fragments persistent in registers ----
    uint32_t qh[4][4];
    {
        uint32_t qa = sb + (uint32_t)((wid * 16 + (lane & 15)) * LDB
                                      + (((lane >> 4) << 3) << 1));
        #pragma unroll
        for (int kt4 = 0; kt4 < 4; kt4++)
            ldsm4(qa + OFF_QHI + (uint32_t)((kt4 * 16) << 1), qh[kt4]);
    }

    float oacc[8][4];
    #pragma unroll
    for (int j = 0; j < 8; j++)
        #pragma unroll
        for (int i = 0; i < 4; i++) oacc[j][i] = 0.f;
    float ls0 = 0.f, ls1 = 0.f;

    for (int kt = 0; kt < ntiles; kt++) {
        const int k0 = kt << 6;
        const uint32_t kvb = OFF_KV0 + (uint32_t)(kt & 1) * KV_SZ;
        const bool have_next = (kt + 1 < ntiles);
        const bool full = (k0 + BK <= valid);

        // ---- prefetch next tile's K/V into registers ----
        if (have_next) {
            const int k0n = k0 + BK;
            #pragma unroll
            for (int it = 0; it < 4; it++) {
                int idx = tid + (it << 8);
                int r = idx >> 4, d4 = (idx & 15) << 2;
                pre[it]     = *(const float4*)(Kb + (size_t)(k0n + r) * DH + d4);
                pre[4 + it] = *(const float4*)(Vb + (size_t)(k0n + r) * DH + d4);
            }
        }

        // ---- GEMM1: S = Q . K, software-pipelined operand loads ----
        const uint32_t kbase = sb + kvb
                             + (uint32_t)((lane & 7) * LDB + (((lane >> 3) << 3) << 1));
        float sacc[8][4];
        uint32_t kh[2][8];
        ldsm4(kbase + REL_KHI, kh[0]); ldsm4(kbase + REL_KHI + 64, kh[0] + 4);
        #pragma unroll
        for (int j = 0; j < 8; j++) {
            if (j < 7) {                     // prefetch next j-group's K fragments
                uint32_t a = kbase + (uint32_t)((j + 1) * 8 * LDB);
                ldsm4(a + REL_KHI, kh[(j + 1) & 1]);
                ldsm4(a + REL_KHI + 64, kh[(j + 1) & 1] + 4);
            }
            #pragma unroll
            for (int i = 0; i < 4; i++) sacc[j][i] = 0.f;
            #pragma unroll
            for (int kt4 = 0; kt4 < 4; kt4++)
                mma16816(sacc[j], qh[kt4], kh[j & 1] + 2 * kt4);
        }

        // ---- exp2 + mask + pack P to fp16 (register-only) ----
        uint32_t ph[8][2];
        #pragma unroll
        for (int j = 0; j < 8; j++) {
            float p0 = ex2f(sacc[j][0]), p1 = ex2f(sacc[j][1]);
            float p2 = ex2f(sacc[j][2]), p3 = ex2f(sacc[j][3]);
            if (!full) {
                int key0 = k0 + j * 8 + ((lane & 3) << 1);
                if (key0     >= valid) { p0 = 0.f; p2 = 0.f; }
                if (key0 + 1 >= valid) { p1 = 0.f; p3 = 0.f; }
            }
            ls0 += p0 + p1; ls1 += p2 + p3;
            ph[j][0] = hpack2(p0, p1);
            ph[j][1] = hpack2(p2, p3);
        }

        // ---- GEMM2: O += P . V, software-pipelined operand loads ----
        #pragma unroll
        for (int t = 0; t < 4; t++) {
            uint32_t Ah[4] = { ph[2*t][0], ph[2*t][1], ph[2*t+1][0], ph[2*t+1][1] };
            int vrow = t * 16 + (((lane >> 3) & 1) << 3) + (lane & 7);
            const uint32_t vbase = sb + kvb
                                 + (uint32_t)(vrow * LDB + (((lane >> 4) << 3) << 1));
            uint32_t vh[2][4];
            ldsm4t(vbase + REL_VHI, vh[0]);
            #pragma unroll
            for (int j2 = 0; j2 < 4; j2++) {
                if (j2 < 3)                  // prefetch next column-group's V fragments
                    ldsm4t(vbase + REL_VHI + (uint32_t)(((j2 + 1) * 16) << 1),
                           vh[(j2 + 1) & 1]);
                mma16816(oacc[2*j2],     Ah, vh[j2 & 1]);
                mma16816(oacc[2*j2 + 1], Ah, vh[j2 & 1] + 2);
            }
        }

        // ---- write next tile into the other buffer; one barrier per tile ----
        if (have_next)
            split_store(pre, smc, OFF_KV0 + (uint32_t)((kt + 1) & 1) * KV_SZ, tid);
        __syncthreads();
    }

    // ---- reduce l across the 4 lanes sharing each row, normalize, store ----
    ls0 += __shfl_xor_sync(0xffffffffu, ls0, 1);
    ls0 += __shfl_xor_sync(0xffffffffu, ls0, 2);
    ls1 += __shfl_xor_sync(0xffffffffu, ls1, 1);
    ls1 += __shfl_xor_sync(0xffffffffu, ls1, 2);
    float inv0 = 1.0f / ls0, inv1 = 1.0f / ls1;

    int g = lane >> 2, c = lane & 3;
    float* r0p = Ob + (wid * 16 + g) * DH;
    float* r1p = r0p + 8 * DH;
    #pragma unroll
    for (int j = 0; j < 8; j++) {
        int col = j * 8 + 2 * c;
        *(float2*)(r0p + col) = make_float2(oacc[j][0] * inv0, oacc[j][1] * inv0);
        *(float2*)(r1p + col) = make_float2(oacc[j][2] * inv1, oacc[j][3] * inv1);
    }
}

extern "C" void kernel_launch(void* const* d_in, const int* in_sizes, int n_in,
                              void* d_out, int out_size) {
    const float* Q  = (const float*)d_in[0];
    const float* K  = (const float*)d_in[1];
    const float* V  = (const float*)d_in[2];
    const int*   VL = (const int*)d_in[3];
    float*       O  = (float*)d_out;
    const int B = in_sizes[3] <= MAXB ? in_sizes[3] : MAXB;

    make_perm<<<1, MAXB>>>(VL, B);

    cudaFuncSetAttribute(fa_hmma, cudaFuncAttributeMaxDynamicSharedMemorySize, SMEM_SZ);
    dim3 grid(SQ / BQ, B);
    fa_hmma<<<grid, 256, SMEM_SZ>>>(Q, K, V, VL, O);
}

// round 15
// speedup vs baseline: 1.0670x; 1.0526x over previous
#include <cuda_runtime.h>
#include <cuda_fp16.h>
#include <cstdint>

#define SQ 2048
#define DH 64
#define BQ 128
#define BK 64
#define LDB 144          // smem row stride in bytes (72 fp16) -> conflict-free ldmatrix

// smem layout: Q (fp16) persistent, then two K/V buffers (fp16)
#define OFF_QHI 0                    // 128 rows * 144B = 18432
#define OFF_KV0 18432                // each buffer: KHI+0, VHI+9216
#define KV_SZ   18432
#define REL_KHI 0
#define REL_VHI 9216
#define SMEM_SZ (OFF_KV0 + 2 * KV_SZ)   // 55296

#define MAXB 64
__device__ int g_perm[MAXB];

__device__ __forceinline__ float ex2f(float x) {
    float r; asm("ex2.approx.f32 %0, %1;" : "=f"(r) : "f"(x)); return r;
}
__device__ __forceinline__ uint32_t smem_u32(const void* p) {
    uint32_t a;
    asm("{ .reg .u64 t; cvta.to.shared.u64 t, %1; cvt.u32.u64 %0, t; }" : "=r"(a) : "l"(p));
    return a;
}
__device__ __forceinline__ uint32_t hpack2(float x0, float x1) {
    __half2 h = __floats2half2_rn(x0, x1);
    return *reinterpret_cast<uint32_t*>(&h);
}
__device__ __forceinline__ void ldsm4(uint32_t a, uint32_t* r) {
    asm volatile("ldmatrix.sync.aligned.m8n8.x4.shared.b16 {%0,%1,%2,%3}, [%4];"
                 : "=r"(r[0]), "=r"(r[1]), "=r"(r[2]), "=r"(r[3]) : "r"(a));
}
__device__ __forceinline__ void ldsm4t(uint32_t a, uint32_t* r) {
    asm volatile("ldmatrix.sync.aligned.m8n8.x4.trans.shared.b16 {%0,%1,%2,%3}, [%4];"
                 : "=r"(r[0]), "=r"(r[1]), "=r"(r[2]), "=r"(r[3]) : "r"(a));
}
__device__ __forceinline__ void mma16816(float* d, const uint32_t* a, const uint32_t* b) {
    asm volatile("mma.sync.aligned.m16n8k16.row.col.f32.f16.f16.f32 "
                 "{%0,%1,%2,%3}, {%4,%5,%6,%7}, {%8,%9}, {%0,%1,%2,%3};"
                 : "+f"(d[0]), "+f"(d[1]), "+f"(d[2]), "+f"(d[3])
                 : "r"(a[0]), "r"(a[1]), "r"(a[2]), "r"(a[3]), "r"(b[0]), "r"(b[1]));
}
// store prefetched K/V tile (fp32 in regs) as fp16 into smem buffer
__device__ __forceinline__ void split_store(const float4* pre, char* smc,
                                            uint32_t bufoff, int tid) {
    #pragma unroll
    for (int it = 0; it < 4; it++) {
        int idx = tid + (it << 8);              // 1024 float4 slots = 64x64
        int r = idx >> 4, d4 = (idx & 15) << 2;
        uint32_t off = bufoff + (uint32_t)(r * LDB + (d4 << 1));
        *(uint2*)(smc + off + REL_KHI) =
            make_uint2(hpack2(pre[it].x, pre[it].y), hpack2(pre[it].z, pre[it].w));
        *(uint2*)(smc + off + REL_VHI) =
            make_uint2(hpack2(pre[4 + it].x, pre[4 + it].y),
                       hpack2(pre[4 + it].z, pre[4 + it].w));
    }
}

// LPT scheduling: rank batches by descending tile count (ties by index).
__global__ void make_perm(const int* __restrict__ VL, int B) {
    int i = threadIdx.x;
    if (i >= B) return;
    int ti = (VL[i] + BK - 1) >> 6;
    int rank = 0;
    for (int j = 0; j < B; j++) {
        int tj = (VL[j] + BK - 1) >> 6;
        if (tj > ti || (tj == ti && j < i)) rank++;
    }
    g_perm[rank] = i;
}

__global__ void __launch_bounds__(256, 1)
fa_hmma(const float* __restrict__ Q, const float* __restrict__ K,
        const float* __restrict__ V, const int* __restrict__ VL,
        float* __restrict__ O)
{
    extern __shared__ __align__(128) char smc[];
    const uint32_t sb = smem_u32(smc);

    const int tid  = threadIdx.x;
    const int wid  = tid >> 5;
    const int lane = tid & 31;
    const int b    = g_perm[blockIdx.y];       // LPT-ordered batch
    const int q0   = blockIdx.x * BQ;
    const int valid = VL[b];

    const float* Qb = Q + ((size_t)b * SQ + q0) * DH;
    const float* Kb = K + (size_t)b * SQ * DH;
    const float* Vb = V + (size_t)b * SQ * DH;
    float*       Ob = O + ((size_t)b * SQ + q0) * DH;

    const int ntiles = (valid + BK - 1) >> 6;   // masked tiles contribute exactly 0

    // ---- prologue: issue tile-0 K/V loads (latency hidden behind Q staging) ----
    float4 pre[8];
    #pragma unroll
    for (int it = 0; it < 4; it++) {
        int idx = tid + (it << 8);
        int r = idx >> 4, d4 = (idx & 15) << 2;
        pre[it]     = *(const float4*)(Kb + (size_t)r * DH + d4);
        pre[4 + it] = *(const float4*)(Vb + (size_t)r * DH + d4);
    }

    // ---- stage Q (scaled by log2e/sqrt(D)) as fp16 into persistent smem ----
    const float qs = 1.4426950408889634f / 8.0f;
    #pragma unroll
    for (int it = 0; it < 8; it++) {
        int idx = tid + (it << 8);              // 2048 float4 slots = 128x64
        int r = idx >> 4, d4 = (idx & 15) << 2;
        float4 qv = *(const float4*)(Qb + r * DH + d4);
        uint32_t off = (uint32_t)(r * LDB + (d4 << 1));
        *(uint2*)(smc + OFF_QHI + off) =
            make_uint2(hpack2(qv.x * qs, qv.y * qs), hpack2(qv.z * qs, qv.w * qs));
    }

    split_store(pre, smc, OFF_KV0, tid);        // tile 0 -> buffer 0
    __syncthreads();

    // ---- Q fragments persistent in registers ----
    uint32_t qh[4][4];
    {
        uint32_t qa = sb + (uint32_t)((wid * 16 + (lane & 15)) * LDB
                                      + (((lane >> 4) << 3) << 1));
        #pragma unroll
        for (int kt4 = 0; kt4 < 4; kt4++)
            ldsm4(qa + OFF_QHI + (uint32_t)((kt4 * 16) << 1), qh[kt4]);
    }

    float oacc[8][4];
    #pragma unroll
    for (int j = 0; j < 8; j++)
        #pragma unroll
        for (int i = 0; i < 4; i++) oacc[j][i] = 0.f;
    float ls0 = 0.f, ls1 = 0.f;

    for (int kt = 0; kt < ntiles; kt++) {
        const int k0 = kt << 6;
        const uint32_t kvb = OFF_KV0 + (uint32_t)(kt & 1) * KV_SZ;
        const bool have_next = (kt + 1 < ntiles);
        const bool full = (k0 + BK <= valid);

        // ---- prefetch next tile's K/V into registers ----
        if (have_next) {
            const int k0n = k0 + BK;
            #pragma unroll
            for (int it = 0; it < 4; it++) {
                int idx = tid + (it << 8);
                int r = idx >> 4, d4 = (idx & 15) << 2;
                pre[it]     = *(const float4*)(Kb + (size_t)(k0n + r) * DH + d4);
                pre[4 + it] = *(const float4*)(Vb + (size_t)(k0n + r) * DH + d4);
            }
        }

        // ---- GEMM1 with lag-1 softmax: exp2/pack of group j-1 issues while
        //      group j's MMAs occupy the tensor pipe (MUFU hides under HMMA).
        //      The 8 sacc chains stay independent (R12 ILP preserved).
        float sacc[8][4];
        uint32_t ph[8][2];
        #pragma unroll
        for (int j = 0; j < 8; j++) {
            #pragma unroll
            for (int i = 0; i < 4; i++) sacc[j][i] = 0.f;
            uint32_t kh[8];
            uint32_t a = sb + kvb
                       + (uint32_t)((j * 8 + (lane & 7)) * LDB + (((lane >> 3) << 3) << 1));
            ldsm4(a + REL_KHI, kh); ldsm4(a + REL_KHI + 64, kh + 4);
            #pragma unroll
            for (int kt4 = 0; kt4 < 4; kt4++) mma16816(sacc[j], qh[kt4], kh + 2 * kt4);

            if (j > 0) {                    // softmax of the PREVIOUS group
                const int jp = j - 1;
                float p0 = ex2f(sacc[jp][0]), p1 = ex2f(sacc[jp][1]);
                float p2 = ex2f(sacc[jp][2]), p3 = ex2f(sacc[jp][3]);
                if (!full) {
                    int key0 = k0 + jp * 8 + ((lane & 3) << 1);
                    if (key0     >= valid) { p0 = 0.f; p2 = 0.f; }
                    if (key0 + 1 >= valid) { p1 = 0.f; p3 = 0.f; }
                }
                ls0 += p0 + p1; ls1 += p2 + p3;
                ph[jp][0] = hpack2(p0, p1);
                ph[jp][1] = hpack2(p2, p3);
            }
        }
        {   // softmax of the last group
            float p0 = ex2f(sacc[7][0]), p1 = ex2f(sacc[7][1]);
            float p2 = ex2f(sacc[7][2]), p3 = ex2f(sacc[7][3]);
            if (!full) {
                int key0 = k0 + 56 + ((lane & 3) << 1);
                if (key0     >= valid) { p0 = 0.f; p2 = 0.f; }
                if (key0 + 1 >= valid) { p1 = 0.f; p3 = 0.f; }
            }
            ls0 += p0 + p1; ls1 += p2 + p3;
            ph[7][0] = hpack2(p0, p1);
            ph[7][1] = hpack2(p2, p3);
        }

        // ---- GEMM2: O += P . V  (monolithic, as in R12) ----
        #pragma unroll
        for (int t = 0; t < 4; t++) {
            uint32_t Ah[4] = { ph[2*t][0], ph[2*t][1], ph[2*t+1][0], ph[2*t+1][1] };
            int vrow = t * 16 + (((lane >> 3) & 1) << 3) + (lane & 7);
            #pragma unroll
            for (int j2 = 0; j2 < 4; j2++) {
                uint32_t vh[4];
                uint32_t a = sb + kvb
                           + (uint32_t)(vrow * LDB + ((j2 * 16 + ((lane >> 4) << 3)) << 1));
                ldsm4t(a + REL_VHI, vh);
                mma16816(oacc[2*j2],     Ah, vh);
                mma16816(oacc[2*j2 + 1], Ah, vh + 2);
            }
        }

        // ---- write next tile into the other buffer; one barrier per tile ----
        if (have_next)
            split_store(pre, smc, OFF_KV0 + (uint32_t)((kt + 1) & 1) * KV_SZ, tid);
        __syncthreads();
    }

    // ---- reduce l across the 4 lanes sharing each row, normalize, store ----
    ls0 += __shfl_xor_sync(0xffffffffu, ls0, 1);
    ls0 += __shfl_xor_sync(0xffffffffu, ls0, 2);
    ls1 += __shfl_xor_sync(0xffffffffu, ls1, 1);
    ls1 += __shfl_xor_sync(0xffffffffu, ls1, 2);
    float inv0 = 1.0f / ls0, inv1 = 1.0f / ls1;

    int g = lane >> 2, c = lane & 3;
    float* r0p = Ob + (wid * 16 + g) * DH;
    float* r1p = r0p + 8 * DH;
    #pragma unroll
    for (int j = 0; j < 8; j++) {
        int col = j * 8 + 2 * c;
        *(float2*)(r0p + col) = make_float2(oacc[j][0] * inv0, oacc[j][1] * inv0);
        *(float2*)(r1p + col) = make_float2(oacc[j][2] * inv1, oacc[j][3] * inv1);
    }
}

extern "C" void kernel_launch(void* const* d_in, const int* in_sizes, int n_in,
                              void* d_out, int out_size) {
    const float* Q  = (const float*)d_in[0];
    const float* K  = (const float*)d_in[1];
    const float* V  = (const float*)d_in[2];
    const int*   VL = (const int*)d_in[3];
    float*       O  = (float*)d_out;
    const int B = in_sizes[3] <= MAXB ? in_sizes[3] : MAXB;

    make_perm<<<1, MAXB>>>(VL, B);

    cudaFuncSetAttribute(fa_hmma, cudaFuncAttributeMaxDynamicSharedMemorySize, SMEM_SZ);
    dim3 grid(SQ / BQ, B);
    fa_hmma<<<grid, 256, SMEM_SZ>>>(Q, K, V, VL, O);
}

// round 16
// speedup vs baseline: 1.0954x; 1.0266x over previous
#include <cuda_runtime.h>
#include <cuda_fp16.h>
#include <cstdint>

#define SQ 2048
#define DH 64
#define BQ 128
#define BK 64
#define LDB 144          // smem row stride in bytes (72 fp16) -> conflict-free ldmatrix

// smem layout: Q (fp16) persistent, then two 128-key K/V buffers (fp16)
#define OFF_QHI 0                    // 128 rows * 144B = 18432
#define OFF_KV0 18432                // each buffer: K(128 rows)+0, V(128 rows)+18432
#define KV_SZ   36864
#define REL_KHI 0
#define REL_VHI 18432
#define HALF_OFF 9216                // 64 rows * 144B
#define SMEM_SZ (OFF_KV0 + 2 * KV_SZ)   // 92160

#define MAXB 64
__device__ int g_perm[MAXB];

__device__ __forceinline__ float ex2f(float x) {
    float r; asm("ex2.approx.f32 %0, %1;" : "=f"(r) : "f"(x)); return r;
}
__device__ __forceinline__ uint32_t smem_u32(const void* p) {
    uint32_t a;
    asm("{ .reg .u64 t; cvta.to.shared.u64 t, %1; cvt.u32.u64 %0, t; }" : "=r"(a) : "l"(p));
    return a;
}
__device__ __forceinline__ uint32_t hpack2(float x0, float x1) {
    __half2 h = __floats2half2_rn(x0, x1);
    return *reinterpret_cast<uint32_t*>(&h);
}
__device__ __forceinline__ void ldsm4(uint32_t a, uint32_t* r) {
    asm volatile("ldmatrix.sync.aligned.m8n8.x4.shared.b16 {%0,%1,%2,%3}, [%4];"
                 : "=r"(r[0]), "=r"(r[1]), "=r"(r[2]), "=r"(r[3]) : "r"(a));
}
__device__ __forceinline__ void ldsm4t(uint32_t a, uint32_t* r) {
    asm volatile("ldmatrix.sync.aligned.m8n8.x4.trans.shared.b16 {%0,%1,%2,%3}, [%4];"
                 : "=r"(r[0]), "=r"(r[1]), "=r"(r[2]), "=r"(r[3]) : "r"(a));
}
__device__ __forceinline__ void mma16816(float* d, const uint32_t* a, const uint32_t* b) {
    asm volatile("mma.sync.aligned.m16n8k16.row.col.f32.f16.f16.f32 "
                 "{%0,%1,%2,%3}, {%4,%5,%6,%7}, {%8,%9}, {%0,%1,%2,%3};"
                 : "+f"(d[0]), "+f"(d[1]), "+f"(d[2]), "+f"(d[3])
                 : "r"(a[0]), "r"(a[1]), "r"(a[2]), "r"(a[3]), "r"(b[0]), "r"(b[1]));
}
// load a 128-row x 64-col fp32 panel into 8 float4 regs per thread
__device__ __forceinline__ void load128(const float* base, float4* pre, int tid) {
    #pragma unroll
    for (int it = 0; it < 8; it++) {
        int idx = tid + (it << 8);              // 2048 float4 slots = 128x64
        int r = idx >> 4, d4 = (idx & 15) << 2;
        pre[it] = *(const float4*)(base + (size_t)r * DH + d4);
    }
}
// store it as fp16 into a 128-row smem panel
__device__ __forceinline__ void store128(const float4* pre, char* smc,
                                         uint32_t dst, int tid) {
    #pragma unroll
    for (int it = 0; it < 8; it++) {
        int idx = tid + (it << 8);
        int r = idx >> 4, d4 = (idx & 15) << 2;
        uint32_t off = dst + (uint32_t)(r * LDB + (d4 << 1));
        *(uint2*)(smc + off) =
            make_uint2(hpack2(pre[it].x, pre[it].y), hpack2(pre[it].z, pre[it].w));
    }
}

// LPT scheduling: rank batches by descending tile count (ties by index).
__global__ void make_perm(const int* __restrict__ VL, int B) {
    int i = threadIdx.x;
    if (i >= B) return;
    int ti = (VL[i] + BK - 1) >> 6;
    int rank = 0;
    for (int j = 0; j < B; j++) {
        int tj = (VL[j] + BK - 1) >> 6;
        if (tj > ti || (tj == ti && j < i)) rank++;
    }
    g_perm[rank] = i;
}

__global__ void __launch_bounds__(256, 1)
fa_hmma(const float* __restrict__ Q, const float* __restrict__ K,
        const float* __restrict__ V, const int* __restrict__ VL,
        float* __restrict__ O)
{
    extern __shared__ __align__(128) char smc[];
    const uint32_t sb = smem_u32(smc);

    const int tid  = threadIdx.x;
    const int wid  = tid >> 5;
    const int lane = tid & 31;
    const int b    = g_perm[blockIdx.y];       // LPT-ordered batch
    const int q0   = blockIdx.x * BQ;
    const int valid = VL[b];

    const float* Qb = Q + ((size_t)b * SQ + q0) * DH;
    const float* Kb = K + (size_t)b * SQ * DH;
    const float* Vb = V + (size_t)b * SQ * DH;
    float*       Ob = O + ((size_t)b * SQ + q0) * DH;

    const int ntiles = (valid + BK - 1) >> 6;   // 64-key tiles (masked ones skipped)
    const int nst    = (ntiles + 1) >> 1;       // 128-key super-tiles

    // ---- prologue ----
    float4 pre[8];
    load128(Kb, pre, tid);                      // tile-0 K (latency hidden by Q staging)

    const float qs = 1.4426950408889634f / 8.0f;
    #pragma unroll
    for (int it = 0; it < 8; it++) {
        int idx = tid + (it << 8);              // 2048 float4 slots = 128x64
        int r = idx >> 4, d4 = (idx & 15) << 2;
        float4 qv = *(const float4*)(Qb + r * DH + d4);
        uint32_t off = (uint32_t)(r * LDB + (d4 << 1));
        *(uint2*)(smc + OFF_QHI + off) =
            make_uint2(hpack2(qv.x * qs, qv.y * qs), hpack2(qv.z * qs, qv.w * qs));
    }
    store128(pre, smc, OFF_KV0 + REL_KHI, tid);
    load128(Vb, pre, tid);
    store128(pre, smc, OFF_KV0 + REL_VHI, tid);
    __syncthreads();

    // ---- Q fragments persistent in registers ----
    uint32_t qh[4][4];
    {
        uint32_t qa = sb + (uint32_t)((wid * 16 + (lane & 15)) * LDB
                                      + (((lane >> 4) << 3) << 1));
        #pragma unroll
        for (int kt4 = 0; kt4 < 4; kt4++)
            ldsm4(qa + OFF_QHI + (uint32_t)((kt4 * 16) << 1), qh[kt4]);
    }

    float oacc[8][4];
    #pragma unroll
    for (int j = 0; j < 8; j++)
        #pragma unroll
        for (int i = 0; i < 4; i++) oacc[j][i] = 0.f;
    float ls0 = 0.f, ls1 = 0.f;

    // ---- 64-key tile body (R15 shape: lag-1 softmax inside GEMM1, monolithic GEMM2)
    auto tile_body = [&](uint32_t base, int k0) {
        const bool full = (k0 + BK <= valid);
        float sacc[8][4];
        uint32_t ph[8][2];
        #pragma unroll
        for (int j = 0; j < 8; j++) {
            #pragma unroll
            for (int i = 0; i < 4; i++) sacc[j][i] = 0.f;
            uint32_t kh[8];
            uint32_t a = base
                       + (uint32_t)((j * 8 + (lane & 7)) * LDB + (((lane >> 3) << 3) << 1));
            ldsm4(a + REL_KHI, kh); ldsm4(a + REL_KHI + 64, kh + 4);
            #pragma unroll
            for (int kt4 = 0; kt4 < 4; kt4++) mma16816(sacc[j], qh[kt4], kh + 2 * kt4);

            if (j > 0) {                    // softmax of the PREVIOUS group
                const int jp = j - 1;
                float p0 = ex2f(sacc[jp][0]), p1 = ex2f(sacc[jp][1]);
                float p2 = ex2f(sacc[jp][2]), p3 = ex2f(sacc[jp][3]);
                if (!full) {
                    int key0 = k0 + jp * 8 + ((lane & 3) << 1);
                    if (key0     >= valid) { p0 = 0.f; p2 = 0.f; }
                    if (key0 + 1 >= valid) { p1 = 0.f; p3 = 0.f; }
                }
                ls0 += p0 + p1; ls1 += p2 + p3;
                ph[jp][0] = hpack2(p0, p1);
                ph[jp][1] = hpack2(p2, p3);
            }
        }
        {   // softmax of the last group
            float p0 = ex2f(sacc[7][0]), p1 = ex2f(sacc[7][1]);
            float p2 = ex2f(sacc[7][2]), p3 = ex2f(sacc[7][3]);
            if (!full) {
                int key0 = k0 + 56 + ((lane & 3) << 1);
                if (key0     >= valid) { p0 = 0.f; p2 = 0.f; }
                if (key0 + 1 >= valid) { p1 = 0.f; p3 = 0.f; }
            }
            ls0 += p0 + p1; ls1 += p2 + p3;
            ph[7][0] = hpack2(p0, p1);
            ph[7][1] = hpack2(p2, p3);
        }

        #pragma unroll
        for (int t = 0; t < 4; t++) {
            uint32_t Ah[4] = { ph[2*t][0], ph[2*t][1], ph[2*t+1][0], ph[2*t+1][1] };
            int vrow = t * 16 + (((lane >> 3) & 1) << 3) + (lane & 7);
            #pragma unroll
            for (int j2 = 0; j2 < 4; j2++) {
                uint32_t vh[4];
                uint32_t a = base
                           + (uint32_t)(vrow * LDB + ((j2 * 16 + ((lane >> 4) << 3)) << 1));
                ldsm4t(a + REL_VHI, vh);
                mma16816(oacc[2*j2],     Ah, vh);
                mma16816(oacc[2*j2 + 1], Ah, vh + 2);
            }
        }
    };

    // ---- super-tile loop: one barrier per 128 keys ----
    for (int s = 0; s < nst; s++) {
        const uint32_t kvb  = OFF_KV0 + (uint32_t)(s & 1) * KV_SZ;
        const uint32_t kvbn = OFF_KV0 + (uint32_t)((s + 1) & 1) * KV_SZ;
        const bool have_next = (s + 1 < nst);
        const int k0 = s << 7;

        if (have_next) load128(Kb + (size_t)(k0 + 128) * DH, pre, tid);

        tile_body(sb + kvb, k0);                            // half 0 (always live)

        if (have_next) {
            store128(pre, smc, kvbn + REL_KHI, tid);
            load128(Vb + (size_t)(k0 + 128) * DH, pre, tid);
        }

        if (2 * s + 1 < ntiles)                             // half 1 (skip if masked)
            tile_body(sb + kvb + HALF_OFF, k0 + 64);

        if (have_next) store128(pre, smc, kvbn + REL_VHI, tid);
        __syncthreads();
    }

    // ---- reduce l across the 4 lanes sharing each row, normalize, store ----
    ls0 += __shfl_xor_sync(0xffffffffu, ls0, 1);
    ls0 += __shfl_xor_sync(0xffffffffu, ls0, 2);
    ls1 += __shfl_xor_sync(0xffffffffu, ls1, 1);
    ls1 += __shfl_xor_sync(0xffffffffu, ls1, 2);
    float inv0 = 1.0f / ls0, inv1 = 1.0f / ls1;

    int g = lane >> 2, c = lane & 3;
    float* r0p = Ob + (wid * 16 + g) * DH;
    float* r1p = r0p + 8 * DH;
    #pragma unroll
    for (int j = 0; j < 8; j++) {
        int col = j * 8 + 2 * c;
        *(float2*)(r0p + col) = make_float2(oacc[j][0] * inv0, oacc[j][1] * inv0);
        *(float2*)(r1p + col) = make_float2(oacc[j][2] * inv1, oacc[j][3] * inv1);
    }
}

extern "C" void kernel_launch(void* const* d_in, const int* in_sizes, int n_in,
                              void* d_out, int out_size) {
    const float* Q  = (const float*)d_in[0];
    const float* K  = (const float*)d_in[1];
    const float* V  = (const float*)d_in[2];
    const int*   VL = (const int*)d_in[3];
    float*       O  = (float*)d_out;
    const int B = in_sizes[3] <= MAXB ? in_sizes[3] : MAXB;

    make_perm<<<1, MAXB>>>(VL, B);

    cudaFuncSetAttribute(fa_hmma, cudaFuncAttributeMaxDynamicSharedMemorySize, SMEM_SZ);
    dim3 grid(SQ / BQ, B);
    fa_hmma<<<grid, 256, SMEM_SZ>>>(Q, K, V, VL, O);
}

// round 17
// speedup vs baseline: 1.1538x; 1.0533x over previous
#include <cuda_runtime.h>
#include <cuda_fp16.h>
#include <cstdint>

#define SQ 2048
#define DH 64
#define BQ 128
#define BK 64
#define LDB 144          // smem row stride in bytes (72 fp16) -> conflict-free ldmatrix

// smem layout: Q (fp16) persistent, then two 128-key K/V buffers (fp16)
#define OFF_QHI 0                    // 128 rows * 144B = 18432
#define OFF_KV0 18432                // each buffer: K(128 rows)+0, V(128 rows)+18432
#define KV_SZ   36864
#define REL_KHI 0
#define REL_VHI 18432
#define HALF_OFF 9216                // 64 rows * 144B
#define SMEM_SZ (OFF_KV0 + 2 * KV_SZ)   // 92160 (x2 CTAs = 184320 <= 227KB)

#define MAXB 64
__device__ int g_perm[MAXB];

__device__ __forceinline__ float ex2f(float x) {
    float r; asm("ex2.approx.f32 %0, %1;" : "=f"(r) : "f"(x)); return r;
}
__device__ __forceinline__ uint32_t smem_u32(const void* p) {
    uint32_t a;
    asm("{ .reg .u64 t; cvta.to.shared.u64 t, %1; cvt.u32.u64 %0, t; }" : "=r"(a) : "l"(p));
    return a;
}
__device__ __forceinline__ uint32_t hpack2(float x0, float x1) {
    __half2 h = __floats2half2_rn(x0, x1);
    return *reinterpret_cast<uint32_t*>(&h);
}
__device__ __forceinline__ void ldsm4(uint32_t a, uint32_t* r) {
    asm volatile("ldmatrix.sync.aligned.m8n8.x4.shared.b16 {%0,%1,%2,%3}, [%4];"
                 : "=r"(r[0]), "=r"(r[1]), "=r"(r[2]), "=r"(r[3]) : "r"(a));
}
__device__ __forceinline__ void ldsm4t(uint32_t a, uint32_t* r) {
    asm volatile("ldmatrix.sync.aligned.m8n8.x4.trans.shared.b16 {%0,%1,%2,%3}, [%4];"
                 : "=r"(r[0]), "=r"(r[1]), "=r"(r[2]), "=r"(r[3]) : "r"(a));
}
__device__ __forceinline__ void mma16816(float* d, const uint32_t* a, const uint32_t* b) {
    asm volatile("mma.sync.aligned.m16n8k16.row.col.f32.f16.f16.f32 "
                 "{%0,%1,%2,%3}, {%4,%5,%6,%7}, {%8,%9}, {%0,%1,%2,%3};"
                 : "+f"(d[0]), "+f"(d[1]), "+f"(d[2]), "+f"(d[3])
                 : "r"(a[0]), "r"(a[1]), "r"(a[2]), "r"(a[3]), "r"(b[0]), "r"(b[1]));
}
// load a 128-row x 64-col fp32 panel into 8 float4 regs per thread
__device__ __forceinline__ void load128(const float* base, float4* pre, int tid) {
    #pragma unroll
    for (int it = 0; it < 8; it++) {
        int idx = tid + (it << 8);              // 2048 float4 slots = 128x64
        int r = idx >> 4, d4 = (idx & 15) << 2;
        pre[it] = *(const float4*)(base + (size_t)r * DH + d4);
    }
}
// store it as fp16 into a 128-row smem panel
__device__ __forceinline__ void store128(const float4* pre, char* smc,
                                         uint32_t dst, int tid) {
    #pragma unroll
    for (int it = 0; it < 8; it++) {
        int idx = tid + (it << 8);
        int r = idx >> 4, d4 = (idx & 15) << 2;
        uint32_t off = dst + (uint32_t)(r * LDB + (d4 << 1));
        *(uint2*)(smc + off) =
            make_uint2(hpack2(pre[it].x, pre[it].y), hpack2(pre[it].z, pre[it].w));
    }
}

// LPT scheduling: rank batches by descending tile count (ties by index).
__global__ void make_perm(const int* __restrict__ VL, int B) {
    int i = threadIdx.x;
    if (i >= B) return;
    int ti = (VL[i] + BK - 1) >> 6;
    int rank = 0;
    for (int j = 0; j < B; j++) {
        int tj = (VL[j] + BK - 1) >> 6;
        if (tj > ti || (tj == ti && j < i)) rank++;
    }
    g_perm[rank] = i;
}

__global__ void __launch_bounds__(256, 2)
fa_hmma(const float* __restrict__ Q, const float* __restrict__ K,
        const float* __restrict__ V, const int* __restrict__ VL,
        float* __restrict__ O)
{
    extern __shared__ __align__(128) char smc[];
    const uint32_t sb = smem_u32(smc);

    const int tid  = threadIdx.x;
    const int wid  = tid >> 5;
    const int lane = tid & 31;
    const int b    = g_perm[blockIdx.y];       // LPT-ordered batch
    const int q0   = blockIdx.x * BQ;
    const int valid = VL[b];

    const float* Qb = Q + ((size_t)b * SQ + q0) * DH;
    const float* Kb = K + (size_t)b * SQ * DH;
    const float* Vb = V + (size_t)b * SQ * DH;
    float*       Ob = O + ((size_t)b * SQ + q0) * DH;

    const int ntiles = (valid + BK - 1) >> 6;   // 64-key tiles (masked ones skipped)
    const int nst    = (ntiles + 1) >> 1;       // 128-key super-tiles

    // ---- prologue ----
    float4 pre[8];
    load128(Kb, pre, tid);                      // tile-0 K (latency hidden by Q staging)

    const float qs = 1.4426950408889634f / 8.0f;
    #pragma unroll
    for (int it = 0; it < 8; it++) {
        int idx = tid + (it << 8);              // 2048 float4 slots = 128x64
        int r = idx >> 4, d4 = (idx & 15) << 2;
        float4 qv = *(const float4*)(Qb + r * DH + d4);
        uint32_t off = (uint32_t)(r * LDB + (d4 << 1));
        *(uint2*)(smc + OFF_QHI + off) =
            make_uint2(hpack2(qv.x * qs, qv.y * qs), hpack2(qv.z * qs, qv.w * qs));
    }
    store128(pre, smc, OFF_KV0 + REL_KHI, tid);
    load128(Vb, pre, tid);
    store128(pre, smc, OFF_KV0 + REL_VHI, tid);
    __syncthreads();

    // ---- Q fragments persistent in registers ----
    uint32_t qh[4][4];
    {
        uint32_t qa = sb + (uint32_t)((wid * 16 + (lane & 15)) * LDB
                                      + (((lane >> 4) << 3) << 1));
        #pragma unroll
        for (int kt4 = 0; kt4 < 4; kt4++)
            ldsm4(qa + OFF_QHI + (uint32_t)((kt4 * 16) << 1), qh[kt4]);
    }

    float oacc[8][4];
    #pragma unroll
    for (int j = 0; j < 8; j++)
        #pragma unroll
        for (int i = 0; i < 4; i++) oacc[j][i] = 0.f;
    float ls0 = 0.f, ls1 = 0.f;

    // ---- 64-key tile body: lag-1 softmax, sacc ring-of-2 (explicit liveness),
    //      monolithic GEMM2 (R15/R16 shape)
    auto tile_body = [&](uint32_t base, int k0) {
        const bool full = (k0 + BK <= valid);
        float sacc[2][4];                       // only groups j and j-1 are live
        uint32_t ph[8][2];
        #pragma unroll
        for (int j = 0; j < 8; j++) {
            float* sc = sacc[j & 1];
            #pragma unroll
            for (int i = 0; i < 4; i++) sc[i] = 0.f;
            uint32_t kh[8];
            uint32_t a = base
                       + (uint32_t)((j * 8 + (lane & 7)) * LDB + (((lane >> 3) << 3) << 1));
            ldsm4(a + REL_KHI, kh); ldsm4(a + REL_KHI + 64, kh + 4);
            #pragma unroll
            for (int kt4 = 0; kt4 < 4; kt4++) mma16816(sc, qh[kt4], kh + 2 * kt4);

            if (j > 0) {                    // softmax of the PREVIOUS group
                const int jp = j - 1;
                const float* sp = sacc[jp & 1];
                float p0 = ex2f(sp[0]), p1 = ex2f(sp[1]);
                float p2 = ex2f(sp[2]), p3 = ex2f(sp[3]);
                if (!full) {
                    int key0 = k0 + jp * 8 + ((lane & 3) << 1);
                    if (key0     >= valid) { p0 = 0.f; p2 = 0.f; }
                    if (key0 + 1 >= valid) { p1 = 0.f; p3 = 0.f; }
                }
                ls0 += p0 + p1; ls1 += p2 + p3;
                ph[jp][0] = hpack2(p0, p1);
                ph[jp][1] = hpack2(p2, p3);
            }
        }
        {   // softmax of the last group (ring slot 7&1 = 1)
            const float* sp = sacc[1];
            float p0 = ex2f(sp[0]), p1 = ex2f(sp[1]);
            float p2 = ex2f(sp[2]), p3 = ex2f(sp[3]);
            if (!full) {
                int key0 = k0 + 56 + ((lane & 3) << 1);
                if (key0     >= valid) { p0 = 0.f; p2 = 0.f; }
                if (key0 + 1 >= valid) { p1 = 0.f; p3 = 0.f; }
            }
            ls0 += p0 + p1; ls1 += p2 + p3;
            ph[7][0] = hpack2(p0, p1);
            ph[7][1] = hpack2(p2, p3);
        }

        #pragma unroll
        for (int t = 0; t < 4; t++) {
            uint32_t Ah[4] = { ph[2*t][0], ph[2*t][1], ph[2*t+1][0], ph[2*t+1][1] };
            int vrow = t * 16 + (((lane >> 3) & 1) << 3) + (lane & 7);
            #pragma unroll
            for (int j2 = 0; j2 < 4; j2++) {
                uint32_t vh[4];
                uint32_t a = base
                           + (uint32_t)(vrow * LDB + ((j2 * 16 + ((lane >> 4) << 3)) << 1));
                ldsm4t(a + REL_VHI, vh);
                mma16816(oacc[2*j2],     Ah, vh);
                mma16816(oacc[2*j2 + 1], Ah, vh + 2);
            }
        }
    };

    // ---- super-tile loop: one barrier per 128 keys ----
    for (int s = 0; s < nst; s++) {
        const uint32_t kvb  = OFF_KV0 + (uint32_t)(s & 1) * KV_SZ;
        const uint32_t kvbn = OFF_KV0 + (uint32_t)((s + 1) & 1) * KV_SZ;
        const bool have_next = (s + 1 < nst);
        const int k0 = s << 7;

        if (have_next) load128(Kb + (size_t)(k0 + 128) * DH, pre, tid);

        tile_body(sb + kvb, k0);                            // half 0 (always live)

        if (have_next) {
            store128(pre, smc, kvbn + REL_KHI, tid);
            load128(Vb + (size_t)(k0 + 128) * DH, pre, tid);
        }

        if (2 * s + 1 < ntiles)                             // half 1 (skip if masked)
            tile_body(sb + kvb + HALF_OFF, k0 + 64);

        if (have_next) store128(pre, smc, kvbn + REL_VHI, tid);
        __syncthreads();
    }

    // ---- reduce l across the 4 lanes sharing each row, normalize, store ----
    ls0 += __shfl_xor_sync(0xffffffffu, ls0, 1);
    ls0 += __shfl_xor_sync(0xffffffffu, ls0, 2);
    ls1 += __shfl_xor_sync(0xffffffffu, ls1, 1);
    ls1 += __shfl_xor_sync(0xffffffffu, ls1, 2);
    float inv0 = 1.0f / ls0, inv1 = 1.0f / ls1;

    int g = lane >> 2, c = lane & 3;
    float* r0p = Ob + (wid * 16 + g) * DH;
    float* r1p = r0p + 8 * DH;
    #pragma unroll
    for (int j = 0; j < 8; j++) {
        int col = j * 8 + 2 * c;
        *(float2*)(r0p + col) = make_float2(oacc[j][0] * inv0, oacc[j][1] * inv0);
        *(float2*)(r1p + col) = make_float2(oacc[j][2] * inv1, oacc[j][3] * inv1);
    }
}

extern "C" void kernel_launch(void* const* d_in, const int* in_sizes, int n_in,
                              void* d_out, int out_size) {
    const float* Q  = (const float*)d_in[0];
    const float* K  = (const float*)d_in[1];
    const float* V  = (const float*)d_in[2];
    const int*   VL = (const int*)d_in[3];
    float*       O  = (float*)d_out;
    const int B = in_sizes[3] <= MAXB ? in_sizes[3] : MAXB;

    make_perm<<<1, MAXB>>>(VL, B);

    cudaFuncSetAttribute(fa_hmma, cudaFuncAttributeMaxDynamicSharedMemorySize, SMEM_SZ);
    dim3 grid(SQ / BQ, B);
    fa_hmma<<<grid, 256, SMEM_SZ>>>(Q, K, V, VL, O);
}